// round 9
// baseline (speedup 1.0000x reference)
#include <cuda_runtime.h>
#include <cuda_fp16.h>
#include <cstdint>

#define NCLS 80
#define NCH  81
#define TK   100
#define BN   8
#define CN   256
#define HN   128
#define WN   128
#define HW   (HN*WN)
#define PP   130
#define NPX  (PP*PP)

// ---------------- scratch (device globals) ---------------------------------
__device__ __half g_xh[(size_t)BN*NPX*CN];   // NHWC padded, fp16-hi
__device__ __half g_xl[(size_t)BN*NPX*CN];   // NHWC padded, fp16-lo
__device__ __half g_wh[9*CN*CN];             // [tap][oc][cin] fp16-hi
__device__ __half g_wl[9*CN*CN];             // [tap][oc][cin] fp16-lo
__device__ float  g_y[(size_t)BN*HW*CN];     // relu(conv3x3), NHWC
__device__ float  g_w2t[CN*NCH];
__device__ float  g_pstar[BN*HW];
__device__ int    g_cls[BN*HW];
__device__ float  g_scores[BN*HW];
__device__ int    g_topidx[BN*TK];

// ---------------- PTX helpers ----------------------------------------------
__device__ __forceinline__ uint32_t smem_u32(const void* p){
    uint32_t a;
    asm("{ .reg .u64 t; cvta.to.shared.u64 t, %1; cvt.u32.u64 %0, t; }" : "=r"(a) : "l"(p));
    return a;
}
__device__ __forceinline__ void cpa16(uint32_t dst, const void* src){
    asm volatile("cp.async.cg.shared.global [%0], [%1], 16;" :: "r"(dst), "l"(src));
}
#define CP_COMMIT() asm volatile("cp.async.commit_group;" ::: "memory")
#define CP_WAIT1()  asm volatile("cp.async.wait_group 1;" ::: "memory")
#define CP_WAIT0()  asm volatile("cp.async.wait_group 0;" ::: "memory")

__device__ __forceinline__ void mma16816(float* d, const uint32_t* a, const uint32_t* b){
    asm volatile("mma.sync.aligned.m16n8k16.row.col.f32.f16.f16.f32 "
        "{%0,%1,%2,%3}, {%4,%5,%6,%7}, {%8,%9}, {%0,%1,%2,%3};"
        : "+f"(d[0]), "+f"(d[1]), "+f"(d[2]), "+f"(d[3])
        : "r"(a[0]), "r"(a[1]), "r"(a[2]), "r"(a[3]), "r"(b[0]), "r"(b[1]));
}
__device__ __forceinline__ void ldm4(uint32_t* r, uint32_t addr){
    asm volatile("ldmatrix.sync.aligned.m8n8.x4.shared.b16 {%0,%1,%2,%3}, [%4];"
        : "=r"(r[0]), "=r"(r[1]), "=r"(r[2]), "=r"(r[3]) : "r"(addr));
}

// ---------------- T0: NCHW -> padded NHWC fp16 hi/lo ------------------------
__global__ __launch_bounds__(256) void t_half(const float* __restrict__ x){
    __shared__ float s[256][33];
    const int b = blockIdx.y;
    const int px0 = blockIdx.x*32;
    const int tid = threadIdx.x;
    const int pxl = tid & 31, cg = tid >> 5;
    const int p = px0 + pxl;
    const int ph = p / PP, pw = p % PP;
    const bool in = (p < NPX) && ph >= 1 && ph <= 128 && pw >= 1 && pw <= 128;
    const float* xp = x + (size_t)b*CN*HW + (size_t)(ph-1)*WN + (pw-1);
    #pragma unroll 8
    for (int i=0;i<32;i++){
        int c = i*8 + cg;
        s[c][pxl] = in ? xp[(size_t)c*HW] : 0.f;
    }
    __syncthreads();
    for (int j=0;j<32;j++){
        int px = px0 + j;
        if (px >= NPX) break;
        float v  = s[tid][j];
        __half hi = __float2half_rn(v);
        __half lo = __float2half_rn(v - __half2float(hi));
        size_t o = ((size_t)b*NPX + px)*CN + tid;
        g_xh[o] = hi;
        g_xl[o] = lo;
    }
}

// ---------------- K0: weight prep + w2t -------------------------------------
__global__ void k0_wprep(const float* __restrict__ w1,
                         const float* __restrict__ w2){
    int t = blockIdx.x*256 + threadIdx.x;
    if (t < 9*CN*CN){
        int tap = t / (CN*CN);
        int r   = t % (CN*CN);
        int oc  = r / CN;
        int cin = r % CN;
        float v  = w1[((size_t)oc*CN + cin)*9 + tap];
        __half hi = __float2half_rn(v);
        __half lo = __float2half_rn(v - __half2float(hi));
        g_wh[t] = hi;     // layout [tap][oc][cin]
        g_wl[t] = lo;
    }
    if (t < CN*NCH){
        int cin = t/NCH, oc = t%NCH;
        g_w2t[t] = w2[oc*CN + cin];
    }
}

// ---------------- K1: conv3x3 via mma.sync fp16 split + ldmatrix ------------
// grid (64 h2, 2 octile, 8 b); 512 threads = 16 warps (4M x 4N), warp m64n32.
// CTA tile: M=256 pixels (2 image rows) x N=128 oc -> B bytes amortized 2x.
// K-loop: 72 steps (9 taps x 8 cin-chunks of 32). 3-stage cp.async pipeline.
// stage: Ah/Al 256x64B (16KB each) + Bh/Bl 128x64B (8KB each) = 48KB;
// XOR swizzle (chunk ^= (row>>1)&3) -> fill & ldmatrix conflict-free.
#define STG_SZ 49152u
#define AH_OFF 0u
#define AL_OFF 16384u
#define BH_OFF 32768u
#define BL_OFF 40960u

__global__ __launch_bounds__(512,1) void kmma(const float* __restrict__ b1){
    extern __shared__ __align__(16) char smem[];
    const uint32_t sb = smem_u32(smem);
    const int tid  = threadIdx.x;
    const int lane = tid & 31, wid = tid >> 5;
    const int wm = wid >> 2, wn = wid & 3;
    const int h2 = blockIdx.x;
    const int ocb = blockIdx.y * 128;
    const int bb = blockIdx.z;

    // fill assignments
    const int arow = tid & 255, aarr = tid >> 8;           // A: all 512 threads
    const uint32_t asw = (uint32_t)((arow >> 1) & 3);
    const __half* axsrc = aarr ? g_xl : g_xh;
    const uint32_t adst = (uint32_t)(aarr ? AL_OFF : AH_OFF) + (uint32_t)arow*64u;

    const int brow = tid & 127, barr = (tid >> 7) & 1;     // B: threads < 256
    const uint32_t bsw = (uint32_t)((brow >> 1) & 3);
    const __half* bwsrc = barr ? g_wl : g_wh;
    const uint32_t bdst = (uint32_t)(barr ? BL_OFF : BH_OFF) + (uint32_t)brow*64u;

    auto load_stage = [&](int g, int buf){
        const int tap = g >> 3, kc = g & 7;
        const int ky = tap/3, kx = tap%3;
        const uint32_t sbase = sb + buf*STG_SZ;
        // A: row arow -> image row 2*h2 + (arow>>7) + ky, col kx + (arow&127)
        const size_t apix = (size_t)bb*NPX
                          + (size_t)(2*h2 + (arow>>7) + ky)*PP + kx + (arow&127);
        const size_t aoff = apix*CN + kc*32;
        #pragma unroll
        for (int c=0;c<4;c++)
            cpa16(sbase + adst + ((uint32_t)c ^ asw)*16u, axsrc + aoff + c*8);
        if (tid < 256){
            const size_t boff = ((size_t)tap*CN + ocb + brow)*CN + kc*32;
            #pragma unroll
            for (int c=0;c<4;c++)
                cpa16(sbase + bdst + ((uint32_t)c ^ bsw)*16u, bwsrc + boff + c*8);
        }
        CP_COMMIT();
    };

    float acc[4][4][4];
    #pragma unroll
    for (int mt=0;mt<4;mt++)
        #pragma unroll
        for (int nt=0;nt<4;nt++)
            #pragma unroll
            for (int q=0;q<4;q++) acc[mt][nt][q] = 0.f;

    load_stage(0, 0);
    load_stage(1, 1);

    // fragment addressing (swizzle keys lane-constant)
    const uint32_t rA  = (uint32_t)(lane & 15);
    const uint32_t sA  = (rA >> 1) & 3;
    const uint32_t cA0 = (uint32_t)(lane >> 4);
    const uint32_t rB  = (uint32_t)((lane & 7) + ((lane >> 4) << 3));
    const uint32_t sB  = (rB >> 1) & 3;
    const uint32_t cB0 = (uint32_t)((lane >> 3) & 1);

    for (int g=0; g<72; g++){
        const int buf = g % 3;
        CP_WAIT1();
        __syncthreads();
        if (g + 2 < 72) load_stage(g+2, (g+2)%3);

        const uint32_t sbase  = sb + buf*STG_SZ;
        const uint32_t aBaseH = sbase + AH_OFF + (uint32_t)(wm*64 + (int)rA)*64u;
        const uint32_t aBaseL = sbase + AL_OFF + (uint32_t)(wm*64 + (int)rA)*64u;
        const uint32_t bBaseH = sbase + BH_OFF + (uint32_t)(wn*32 + (int)rB)*64u;
        const uint32_t bBaseL = sbase + BL_OFF + (uint32_t)(wn*32 + (int)rB)*64u;

        #pragma unroll
        for (int kc16=0; kc16<2; kc16++){
            const uint32_t gA = ((uint32_t)(kc16*2) + cA0) ^ sA;
            const uint32_t gB = ((uint32_t)(kc16*2) + cB0) ^ sB;

            uint32_t bh[4][2], bl[4][2];
            #pragma unroll
            for (int nt2=0; nt2<2; nt2++){
                uint32_t r[4];
                ldm4(r, bBaseH + (uint32_t)(nt2*16)*64u + gB*16u);
                bh[nt2*2+0][0]=r[0]; bh[nt2*2+0][1]=r[1];
                bh[nt2*2+1][0]=r[2]; bh[nt2*2+1][1]=r[3];
                ldm4(r, bBaseL + (uint32_t)(nt2*16)*64u + gB*16u);
                bl[nt2*2+0][0]=r[0]; bl[nt2*2+0][1]=r[1];
                bl[nt2*2+1][0]=r[2]; bl[nt2*2+1][1]=r[3];
            }
            uint32_t ah[4][4], al[4][4];
            #pragma unroll
            for (int mt=0;mt<4;mt++){
                ldm4(ah[mt], aBaseH + (uint32_t)(mt*16)*64u + gA*16u);
                ldm4(al[mt], aBaseL + (uint32_t)(mt*16)*64u + gA*16u);
            }
            #pragma unroll
            for (int mt=0;mt<4;mt++)
                #pragma unroll
                for (int nt=0;nt<4;nt++){
                    mma16816(acc[mt][nt], ah[mt], bh[nt]);
                    mma16816(acc[mt][nt], ah[mt], bl[nt]);
                    mma16816(acc[mt][nt], al[mt], bh[nt]);
                }
        }
    }
    CP_WAIT0();

    // epilogue: bias + relu -> y NHWC (two image rows)
    #pragma unroll
    for (int nt=0;nt<4;nt++){
        const int cc = ocb + wn*32 + nt*8 + (lane & 3)*2;
        const float bz0 = b1[cc], bz1 = b1[cc+1];
        #pragma unroll
        for (int mt=0;mt<4;mt++){
            const int p0 = wm*64 + mt*16 + (lane >> 2);    // 0..255
            const int p1 = p0 + 8;
            const size_t pix0 = (size_t)bb*HW + (size_t)(2*h2 + (p0>>7))*WN + (p0&127);
            const size_t pix1 = (size_t)bb*HW + (size_t)(2*h2 + (p1>>7))*WN + (p1&127);
            float2 v0, v1;
            v0.x = fmaxf(acc[mt][nt][0] + bz0, 0.f);
            v0.y = fmaxf(acc[mt][nt][1] + bz1, 0.f);
            v1.x = fmaxf(acc[mt][nt][2] + bz0, 0.f);
            v1.y = fmaxf(acc[mt][nt][3] + bz1, 0.f);
            *(float2*)&g_y[pix0*CN + cc] = v0;
            *(float2*)&g_y[pix1*CN + cc] = v1;
        }
    }
}

// ---------------- K2: conv1x1 + bias + softmax stats + logits out ----------
__global__ __launch_bounds__(256,2) void k2_conv1(const float* __restrict__ b2,
                                                  float* __restrict__ out){
    __shared__ __align__(16) float ws2[32][84];
    const int tid = threadIdx.x;
    const int gp  = blockIdx.x*256 + tid;
    const int b   = gp >> 14, hw = gp & (HW-1);

    float acc[NCH];
    #pragma unroll
    for (int o=0;o<NCH;o++) acc[o] = 0.f;

    const float* yb = g_y + (size_t)gp*CN;      // NHWC: contiguous 256 per pixel
    for (int cc=0; cc<CN; cc+=32){
        __syncthreads();
        #pragma unroll
        for (int i=tid; i<32*NCH; i+=256)
            ws2[i/NCH][i%NCH] = g_w2t[(cc + i/NCH)*NCH + (i%NCH)];
        __syncthreads();
        #pragma unroll
        for (int j=0;j<8;j++){
            const float4 v4 = *(const float4*)(yb + cc + j*4);
            const float vv[4] = {v4.x, v4.y, v4.z, v4.w};
            #pragma unroll
            for (int u=0;u<4;u++){
                const int cl = j*4 + u;
                const float v = vv[u];
                #pragma unroll
                for (int o4=0;o4<20;o4++){
                    float4 w4 = *(const float4*)&ws2[cl][o4*4];
                    acc[o4*4+0] += v*w4.x; acc[o4*4+1] += v*w4.y;
                    acc[o4*4+2] += v*w4.z; acc[o4*4+3] += v*w4.w;
                }
                acc[80] += v*ws2[cl][80];
            }
        }
    }
    #pragma unroll
    for (int o=0;o<NCH;o++) acc[o] += b2[o];

    float m = acc[0];
    #pragma unroll
    for (int o=1;o<NCH;o++) m = fmaxf(m, acc[o]);
    float s = 0.f;
    #pragma unroll
    for (int o=0;o<NCH;o++) s += expf(acc[o]-m);
    int cls = 0; float best = acc[0];
    #pragma unroll
    for (int o=1;o<NCLS;o++) if (acc[o] > best){ best = acc[o]; cls = o; }

    g_pstar[gp] = expf(best - m)/s;
    g_cls[gp]   = cls;

    float* lo = out + 409600 + (size_t)b*NCH*HW + hw;
    #pragma unroll
    for (int o=0;o<NCH;o++) lo[(size_t)o*HW] = acc[o];
}

// ---------------- K3: local-max boost + score map --------------------------
__global__ void k3_boost(){
    const int gp = blockIdx.x*256 + threadIdx.x;
    const int b = gp>>14, hw = gp&(HW-1);
    const int h = hw>>7,  w  = hw&127;
    const float p = g_pstar[gp];
    const int   c = g_cls[gp];
    bool ok = (p >= 1e-6f);
    #pragma unroll
    for (int dy=-1; dy<=1; dy++)
        #pragma unroll
        for (int dx=-1; dx<=1; dx++){
            if (dy==0 && dx==0) continue;
            int nh = h+dy, nw = w+dx;
            if (nh<0 || nh>=HN || nw<0 || nw>=WN) continue;
            int n = (b<<14) + nh*WN + nw;
            if (g_cls[n]==c && p < g_pstar[n]) ok = false;
        }
    g_scores[gp] = p + (ok ? 1.f : 0.f);
}

// ---------------- K4: per-batch top-100 via bitonic sort -------------------
__global__ void k4_topk(){
    extern __shared__ unsigned long long sk[];
    const int N = HW;
    const int b = blockIdx.x, tid = threadIdx.x;
    for (int i=tid; i<N; i+=1024){
        unsigned sb2 = __float_as_uint(g_scores[(b<<14)+i]);
        sk[i] = ((unsigned long long)sb2<<32) | (unsigned)(0xFFFFFFFFu - (unsigned)i);
    }
    __syncthreads();
    for (int k=2; k<=N; k<<=1){
        for (int j=k>>1; j>0; j>>=1){
            for (int i=tid; i<N; i+=1024){
                int ixj = i^j;
                if (ixj > i){
                    unsigned long long a = sk[i], c = sk[ixj];
                    bool up = (i&k)==0;
                    if (up ? (a<c) : (a>c)){ sk[i]=c; sk[ixj]=a; }
                }
            }
            __syncthreads();
        }
    }
    if (tid < TK){
        unsigned low = (unsigned)sk[tid];
        g_topidx[b*TK + tid] = (int)(0xFFFFFFFFu - low);
    }
}

// ---------------- K5: gather proposals + pos embeddings --------------------
__global__ void k5_gather(const float* __restrict__ x,
                          const float* __restrict__ pe,
                          float* __restrict__ out){
    const int t = blockIdx.x*256 + threadIdx.x;
    if (t >= BN*CN*TK) return;
    const int k = t % TK;
    const int c = (t / TK) % CN;
    const int b = t / (TK*CN);
    const int idx = g_topidx[b*TK + k];
    out[t]            = x [(size_t)(b*CN + c)*HW + idx];
    out[BN*CN*TK + t] = pe[(size_t)c*HW + idx];
}

// ---------------- launch ----------------------------------------------------
extern "C" void kernel_launch(void* const* d_in, const int* in_sizes, int n_in,
                              void* d_out, int out_size){
    const float* x  = (const float*)d_in[0];
    const float* pe = (const float*)d_in[1];
    const float* w1 = (const float*)d_in[2];
    const float* b1 = (const float*)d_in[3];
    const float* w2 = (const float*)d_in[4];
    const float* b2 = (const float*)d_in[5];
    float* out = (float*)d_out;

    cudaFuncSetAttribute(kmma,   cudaFuncAttributeMaxDynamicSharedMemorySize, 3*STG_SZ);
    cudaFuncSetAttribute(k4_topk, cudaFuncAttributeMaxDynamicSharedMemorySize, 131072);

    dim3 gt((NPX + 31)/32, BN);
    t_half<<<gt, 256>>>(x);
    k0_wprep<<<(9*CN*CN + 255)/256, 256>>>(w1, w2);

    dim3 gg(64, 2, BN);
    kmma<<<gg, 512, 3*STG_SZ>>>(b1);

    k2_conv1<<<(BN*HW)/256, 256>>>(b2, out);
    k3_boost<<<(BN*HW)/256, 256>>>();
    k4_topk<<<BN, 1024, 131072>>>();
    k5_gather<<<(BN*CN*TK + 255)/256, 256>>>(x, pe, out);
}

// round 11
// speedup vs baseline: 1.2754x; 1.2754x over previous
#include <cuda_runtime.h>
#include <cuda_fp16.h>
#include <cstdint>

#define NCLS 80
#define NCH  81
#define TK   100
#define BN   8
#define CN   256
#define HN   128
#define WN   128
#define HW   (HN*WN)
#define PP   130
#define NPX  (PP*PP)

// ---------------- scratch (device globals) ---------------------------------
__device__ __half g_xh[(size_t)BN*NPX*CN];   // NHWC padded, fp16-hi
__device__ __half g_xl[(size_t)BN*NPX*CN];   // NHWC padded, fp16-lo
// B in mma-fragment order: [tap*8+kc][kc16][ogp(16)][lane(32)] -> uint4
__device__ uint4  g_wfh[73728];              // 9*8*2*16*32 uint4
__device__ uint4  g_wfl[73728];
__device__ float  g_y[(size_t)BN*HW*CN];     // relu(conv3x3), NHWC
__device__ float  g_w2t[CN*NCH];
__device__ float  g_pstar[BN*HW];
__device__ int    g_cls[BN*HW];
__device__ float  g_scores[BN*HW];
__device__ int    g_topidx[BN*TK];

// ---------------- PTX helpers ----------------------------------------------
__device__ __forceinline__ uint32_t smem_u32(const void* p){
    uint32_t a;
    asm("{ .reg .u64 t; cvta.to.shared.u64 t, %1; cvt.u32.u64 %0, t; }" : "=r"(a) : "l"(p));
    return a;
}
__device__ __forceinline__ void cpa16(uint32_t dst, const void* src){
    asm volatile("cp.async.cg.shared.global [%0], [%1], 16;" :: "r"(dst), "l"(src));
}
#define CP_COMMIT() asm volatile("cp.async.commit_group;" ::: "memory")
#define CP_WAIT2()  asm volatile("cp.async.wait_group 2;" ::: "memory")
#define CP_WAIT0()  asm volatile("cp.async.wait_group 0;" ::: "memory")

__device__ __forceinline__ void mma16816(float* d, const uint32_t* a, const uint32_t* b){
    asm volatile("mma.sync.aligned.m16n8k16.row.col.f32.f16.f16.f32 "
        "{%0,%1,%2,%3}, {%4,%5,%6,%7}, {%8,%9}, {%0,%1,%2,%3};"
        : "+f"(d[0]), "+f"(d[1]), "+f"(d[2]), "+f"(d[3])
        : "r"(a[0]), "r"(a[1]), "r"(a[2]), "r"(a[3]), "r"(b[0]), "r"(b[1]));
}
__device__ __forceinline__ void ldm4(uint32_t* r, uint32_t addr){
    asm volatile("ldmatrix.sync.aligned.m8n8.x4.shared.b16 {%0,%1,%2,%3}, [%4];"
        : "=r"(r[0]), "=r"(r[1]), "=r"(r[2]), "=r"(r[3]) : "r"(addr));
}

// ---------------- T0: NCHW -> padded NHWC fp16 hi/lo ------------------------
__global__ __launch_bounds__(256) void t_half(const float* __restrict__ x){
    __shared__ float s[256][33];
    const int b = blockIdx.y;
    const int px0 = blockIdx.x*32;
    const int tid = threadIdx.x;
    const int pxl = tid & 31, cg = tid >> 5;
    const int p = px0 + pxl;
    const int ph = p / PP, pw = p % PP;
    const bool in = (p < NPX) && ph >= 1 && ph <= 128 && pw >= 1 && pw <= 128;
    const float* xp = x + (size_t)b*CN*HW + (size_t)(ph-1)*WN + (pw-1);
    #pragma unroll 8
    for (int i=0;i<32;i++){
        int c = i*8 + cg;
        s[c][pxl] = in ? xp[(size_t)c*HW] : 0.f;
    }
    __syncthreads();
    for (int j=0;j<32;j++){
        int px = px0 + j;
        if (px >= NPX) break;
        float v  = s[tid][j];
        __half hi = __float2half_rn(v);
        __half lo = __float2half_rn(v - __half2float(hi));
        size_t o = ((size_t)b*NPX + px)*CN + tid;
        g_xh[o] = hi;
        g_xl[o] = lo;
    }
}

// ---------------- K0: weight prep (fragment order) + w2t --------------------
// u32 element t: j=t&3, l=(t>>2)&31, ogp=(t>>7)&15, kc16=(t>>11)&1,
// kc=(t>>12)&7, tap=t>>15.  og=ogp*2+(j>>1); oc=og*8+l/4;
// k = kc*32 + kc16*16 + (j&1)*8 + (l%4)*2  (+0,+1)
__global__ void k0_wprep(const float* __restrict__ w1,
                         const float* __restrict__ w2){
    int t = blockIdx.x*256 + threadIdx.x;
    if (t < 9*8*2*16*32*4){
        int j    = t & 3;
        int l    = (t>>2) & 31;
        int ogp  = (t>>7) & 15;
        int kc16 = (t>>11) & 1;
        int kc   = (t>>12) & 7;
        int tap  = t >> 15;
        int oc = (ogp*2 + (j>>1))*8 + (l>>2);
        int k  = kc*32 + kc16*16 + (j&1)*8 + (l&3)*2;
        float v0 = w1[((size_t)oc*CN + k  )*9 + tap];
        float v1 = w1[((size_t)oc*CN + k+1)*9 + tap];
        __half h0 = __float2half_rn(v0);
        __half h1 = __float2half_rn(v1);
        __half l0 = __float2half_rn(v0 - __half2float(h0));
        __half l1 = __float2half_rn(v1 - __half2float(h1));
        ((uint32_t*)g_wfh)[t] = (uint32_t)__half_as_ushort(h0) |
                                ((uint32_t)__half_as_ushort(h1) << 16);
        ((uint32_t*)g_wfl)[t] = (uint32_t)__half_as_ushort(l0) |
                                ((uint32_t)__half_as_ushort(l1) << 16);
    }
    if (t < CN*NCH){
        int cin = t/NCH, oc = t%NCH;
        g_w2t[t] = w2[oc*CN + cin];
    }
}

// ---------------- K1: conv3x3 via mma.sync fp16 split ------------------------
// grid (128 h, 2 octile, 8 b); 256 threads = 8 warps (2M x 4N), warp m64n32.
// A: 4-stage cp.async ring (Ah/Al 8KB each = 16KB/stage, 64KB total), XOR
// swizzle, ldmatrix. B: direct LDG.128 from fragment-ordered g_wfh/g_wfl
// (L1/L2 resident; no smem, no ldmatrix). 2 CTAs/SM.
#define STG_SZ 16384u
#define AL_OFF 8192u

__global__ __launch_bounds__(256,2) void kmma(const float* __restrict__ b1){
    extern __shared__ __align__(16) char smem[];
    const uint32_t sb = smem_u32(smem);
    const int tid  = threadIdx.x;
    const int lane = tid & 31, wid = tid >> 5;
    const int wm = wid >> 2, wn = wid & 3;
    const int h  = blockIdx.x;
    const int ocb = blockIdx.y * 128;
    const int bb = blockIdx.z;

    // A fill: row = tid>>1, chunks c = 2*(tid&1)+{0,1}, swizzle s=(row>>1)&3
    const int lrow = tid >> 1, lhalf = tid & 1;
    const uint32_t ssw = (uint32_t)((lrow >> 1) & 3);
    const int c0 = 2*lhalf;
    const uint32_t d0 = lrow*64u + ((uint32_t)(c0  ) ^ ssw)*16u;
    const uint32_t d1 = lrow*64u + ((uint32_t)(c0+1) ^ ssw)*16u;

    auto load_stage = [&](int g, int buf){
        const int tap = g >> 3, kc = g & 7;
        const int ky = tap/3, kx = tap%3;
        const uint32_t sbase = sb + buf*STG_SZ;
        const size_t apix = (size_t)bb*NPX + (size_t)(h + ky)*PP + kx + lrow;
        const size_t aoff = apix*CN + kc*32 + c0*8;
        cpa16(sbase          + d0, g_xh + aoff);
        cpa16(sbase          + d1, g_xh + aoff + 8);
        cpa16(sbase + AL_OFF + d0, g_xl + aoff);
        cpa16(sbase + AL_OFF + d1, g_xl + aoff + 8);
        CP_COMMIT();
    };

    float acc[4][4][4];
    #pragma unroll
    for (int mt=0;mt<4;mt++)
        #pragma unroll
        for (int nt=0;nt<4;nt++)
            #pragma unroll
            for (int q=0;q<4;q++) acc[mt][nt][q] = 0.f;

    load_stage(0, 0);
    load_stage(1, 1);
    load_stage(2, 2);

    // A fragment addressing (swizzle key lane-constant)
    const uint32_t rA  = (uint32_t)(lane & 15);
    const uint32_t sA  = (rA >> 1) & 3;
    const uint32_t cA0 = (uint32_t)(lane >> 4);
    const int ogp_base = blockIdx.y*8 + wn*2;   // oc-tile offset + warp column

    for (int g=0; g<72; g++){
        const int buf = g & 3;
        CP_WAIT2();
        __syncthreads();
        if (g + 3 < 72) load_stage(g+3, (g+3)&3);

        const uint32_t sbase  = sb + buf*STG_SZ;
        const uint32_t aBaseH = sbase          + (uint32_t)(wm*64 + (int)rA)*64u;
        const uint32_t aBaseL = sbase + AL_OFF + (uint32_t)(wm*64 + (int)rA)*64u;

        #pragma unroll
        for (int kc16=0; kc16<2; kc16++){
            // B fragments: direct LDG.128, fragment-ordered
            const int fb = ((g*2 + kc16)*16 + ogp_base)*32 + lane;
            const uint4 bq0 = __ldg(&g_wfh[fb]);
            const uint4 bq1 = __ldg(&g_wfh[fb + 32]);
            const uint4 cq0 = __ldg(&g_wfl[fb]);
            const uint4 cq1 = __ldg(&g_wfl[fb + 32]);
            uint32_t bh[4][2] = {{bq0.x,bq0.y},{bq0.z,bq0.w},{bq1.x,bq1.y},{bq1.z,bq1.w}};
            uint32_t bl[4][2] = {{cq0.x,cq0.y},{cq0.z,cq0.w},{cq1.x,cq1.y},{cq1.z,cq1.w}};

            const uint32_t gA = ((uint32_t)(kc16*2) + cA0) ^ sA;
            uint32_t ah[4][4], al[4][4];
            #pragma unroll
            for (int mt=0;mt<4;mt++){
                ldm4(ah[mt], aBaseH + (uint32_t)(mt*16)*64u + gA*16u);
                ldm4(al[mt], aBaseL + (uint32_t)(mt*16)*64u + gA*16u);
            }
            #pragma unroll
            for (int mt=0;mt<4;mt++)
                #pragma unroll
                for (int nt=0;nt<4;nt++){
                    mma16816(acc[mt][nt], ah[mt], bh[nt]);
                    mma16816(acc[mt][nt], ah[mt], bl[nt]);
                    mma16816(acc[mt][nt], al[mt], bh[nt]);
                }
        }
    }
    CP_WAIT0();

    // epilogue: bias + relu -> y NHWC
    #pragma unroll
    for (int nt=0;nt<4;nt++){
        const int cc = ocb + wn*32 + nt*8 + (lane & 3)*2;
        const float bz0 = b1[cc], bz1 = b1[cc+1];
        #pragma unroll
        for (int mt=0;mt<4;mt++){
            const int w = wm*64 + mt*16 + (lane >> 2);
            const size_t pix = (size_t)bb*HW + (size_t)h*WN + w;
            float2 v0, v1;
            v0.x = fmaxf(acc[mt][nt][0] + bz0, 0.f);
            v0.y = fmaxf(acc[mt][nt][1] + bz1, 0.f);
            v1.x = fmaxf(acc[mt][nt][2] + bz0, 0.f);
            v1.y = fmaxf(acc[mt][nt][3] + bz1, 0.f);
            *(float2*)&g_y[pix*CN + cc]     = v0;
            *(float2*)&g_y[(pix+8)*CN + cc] = v1;
        }
    }
}

// ---------------- K2: conv1x1 + bias + softmax stats + logits out ----------
__global__ __launch_bounds__(256,2) void k2_conv1(const float* __restrict__ b2,
                                                  float* __restrict__ out){
    __shared__ __align__(16) float ws2[32][84];
    const int tid = threadIdx.x;
    const int gp  = blockIdx.x*256 + tid;
    const int b   = gp >> 14, hw = gp & (HW-1);

    float acc[NCH];
    #pragma unroll
    for (int o=0;o<NCH;o++) acc[o] = 0.f;

    const float* yb = g_y + (size_t)gp*CN;      // NHWC: contiguous 256 per pixel
    for (int cc=0; cc<CN; cc+=32){
        __syncthreads();
        #pragma unroll
        for (int i=tid; i<32*NCH; i+=256)
            ws2[i/NCH][i%NCH] = g_w2t[(cc + i/NCH)*NCH + (i%NCH)];
        __syncthreads();
        #pragma unroll
        for (int j=0;j<8;j++){
            const float4 v4 = *(const float4*)(yb + cc + j*4);
            const float vv[4] = {v4.x, v4.y, v4.z, v4.w};
            #pragma unroll
            for (int u=0;u<4;u++){
                const int cl = j*4 + u;
                const float v = vv[u];
                #pragma unroll
                for (int o4=0;o4<20;o4++){
                    float4 w4 = *(const float4*)&ws2[cl][o4*4];
                    acc[o4*4+0] += v*w4.x; acc[o4*4+1] += v*w4.y;
                    acc[o4*4+2] += v*w4.z; acc[o4*4+3] += v*w4.w;
                }
                acc[80] += v*ws2[cl][80];
            }
        }
    }
    #pragma unroll
    for (int o=0;o<NCH;o++) acc[o] += b2[o];

    float m = acc[0];
    #pragma unroll
    for (int o=1;o<NCH;o++) m = fmaxf(m, acc[o]);
    float s = 0.f;
    #pragma unroll
    for (int o=0;o<NCH;o++) s += expf(acc[o]-m);
    int cls = 0; float best = acc[0];
    #pragma unroll
    for (int o=1;o<NCLS;o++) if (acc[o] > best){ best = acc[o]; cls = o; }

    g_pstar[gp] = expf(best - m)/s;
    g_cls[gp]   = cls;

    float* lo = out + 409600 + (size_t)b*NCH*HW + hw;
    #pragma unroll
    for (int o=0;o<NCH;o++) lo[(size_t)o*HW] = acc[o];
}

// ---------------- K3: local-max boost + score map --------------------------
__global__ void k3_boost(){
    const int gp = blockIdx.x*256 + threadIdx.x;
    const int b = gp>>14, hw = gp&(HW-1);
    const int h = hw>>7,  w  = hw&127;
    const float p = g_pstar[gp];
    const int   c = g_cls[gp];
    bool ok = (p >= 1e-6f);
    #pragma unroll
    for (int dy=-1; dy<=1; dy++)
        #pragma unroll
        for (int dx=-1; dx<=1; dx++){
            if (dy==0 && dx==0) continue;
            int nh = h+dy, nw = w+dx;
            if (nh<0 || nh>=HN || nw<0 || nw>=WN) continue;
            int n = (b<<14) + nh*WN + nw;
            if (g_cls[n]==c && p < g_pstar[n]) ok = false;
        }
    g_scores[gp] = p + (ok ? 1.f : 0.f);
}

// ---------------- K4: per-batch top-100 via bitonic sort -------------------
__global__ void k4_topk(){
    extern __shared__ unsigned long long sk[];
    const int N = HW;
    const int b = blockIdx.x, tid = threadIdx.x;
    for (int i=tid; i<N; i+=1024){
        unsigned sb2 = __float_as_uint(g_scores[(b<<14)+i]);
        sk[i] = ((unsigned long long)sb2<<32) | (unsigned)(0xFFFFFFFFu - (unsigned)i);
    }
    __syncthreads();
    for (int k=2; k<=N; k<<=1){
        for (int j=k>>1; j>0; j>>=1){
            for (int i=tid; i<N; i+=1024){
                int ixj = i^j;
                if (ixj > i){
                    unsigned long long a = sk[i], c = sk[ixj];
                    bool up = (i&k)==0;
                    if (up ? (a<c) : (a>c)){ sk[i]=c; sk[ixj]=a; }
                }
            }
            __syncthreads();
        }
    }
    if (tid < TK){
        unsigned low = (unsigned)sk[tid];
        g_topidx[b*TK + tid] = (int)(0xFFFFFFFFu - low);
    }
}

// ---------------- K5: gather proposals + pos embeddings --------------------
__global__ void k5_gather(const float* __restrict__ x,
                          const float* __restrict__ pe,
                          float* __restrict__ out){
    const int t = blockIdx.x*256 + threadIdx.x;
    if (t >= BN*CN*TK) return;
    const int k = t % TK;
    const int c = (t / TK) % CN;
    const int b = t / (TK*CN);
    const int idx = g_topidx[b*TK + k];
    out[t]            = x [(size_t)(b*CN + c)*HW + idx];
    out[BN*CN*TK + t] = pe[(size_t)c*HW + idx];
}

// ---------------- launch ----------------------------------------------------
extern "C" void kernel_launch(void* const* d_in, const int* in_sizes, int n_in,
                              void* d_out, int out_size){
    const float* x  = (const float*)d_in[0];
    const float* pe = (const float*)d_in[1];
    const float* w1 = (const float*)d_in[2];
    const float* b1 = (const float*)d_in[3];
    const float* w2 = (const float*)d_in[4];
    const float* b2 = (const float*)d_in[5];
    float* out = (float*)d_out;

    cudaFuncSetAttribute(kmma,   cudaFuncAttributeMaxDynamicSharedMemorySize, 4*STG_SZ);
    cudaFuncSetAttribute(k4_topk, cudaFuncAttributeMaxDynamicSharedMemorySize, 131072);

    dim3 gt((NPX + 31)/32, BN);
    t_half<<<gt, 256>>>(x);
    k0_wprep<<<(9*8*2*16*32*4 + 255)/256, 256>>>(w1, w2);

    dim3 gg(128, 2, BN);
    kmma<<<gg, 256, 4*STG_SZ>>>(b1);

    k2_conv1<<<(BN*HW)/256, 256>>>(b2, out);
    k3_boost<<<(BN*HW)/256, 256>>>();
    k4_topk<<<BN, 1024, 131072>>>();
    k5_gather<<<(BN*CN*TK + 255)/256, 256>>>(x, pe, out);
}

// round 12
// speedup vs baseline: 1.2913x; 1.0125x over previous
#include <cuda_runtime.h>
#include <cuda_fp16.h>
#include <cstdint>

#define NCLS 80
#define NCH  81
#define TK   100
#define BN   8
#define CN   256
#define HN   128
#define WN   128
#define HW   (HN*WN)
#define PP   130
#define NPX  (PP*PP)

// ---------------- scratch (device globals) ---------------------------------
__device__ __half g_xh[(size_t)BN*NPX*CN];   // NHWC padded, fp16-hi
__device__ __half g_xl[(size_t)BN*NPX*CN];   // NHWC padded, fp16-lo
// B in mma-fragment order: [k16 index][ogp(16)][lane(32)] -> uint4
__device__ uint4  g_wfh[73728];              // 144*16*32 uint4
__device__ uint4  g_wfl[73728];
__device__ float  g_y[(size_t)BN*HW*CN];     // relu(conv3x3), NHWC
__device__ float  g_w2t[CN*NCH];
__device__ float  g_pstar[BN*HW];
__device__ int    g_cls[BN*HW];
__device__ float  g_scores[BN*HW];
__device__ int    g_topidx[BN*TK];

// ---------------- PTX helpers ----------------------------------------------
__device__ __forceinline__ uint32_t smem_u32(const void* p){
    uint32_t a;
    asm("{ .reg .u64 t; cvta.to.shared.u64 t, %1; cvt.u32.u64 %0, t; }" : "=r"(a) : "l"(p));
    return a;
}
__device__ __forceinline__ void cpa16(uint32_t dst, const void* src){
    asm volatile("cp.async.cg.shared.global [%0], [%1], 16;" :: "r"(dst), "l"(src));
}
#define CP_COMMIT() asm volatile("cp.async.commit_group;" ::: "memory")
#define CP_WAIT1()  asm volatile("cp.async.wait_group 1;" ::: "memory")
#define CP_WAIT0()  asm volatile("cp.async.wait_group 0;" ::: "memory")

__device__ __forceinline__ void mma16816(float* d, const uint32_t* a, const uint32_t* b){
    asm volatile("mma.sync.aligned.m16n8k16.row.col.f32.f16.f16.f32 "
        "{%0,%1,%2,%3}, {%4,%5,%6,%7}, {%8,%9}, {%0,%1,%2,%3};"
        : "+f"(d[0]), "+f"(d[1]), "+f"(d[2]), "+f"(d[3])
        : "r"(a[0]), "r"(a[1]), "r"(a[2]), "r"(a[3]), "r"(b[0]), "r"(b[1]));
}
__device__ __forceinline__ void ldm4(uint32_t* r, uint32_t addr){
    asm volatile("ldmatrix.sync.aligned.m8n8.x4.shared.b16 {%0,%1,%2,%3}, [%4];"
        : "=r"(r[0]), "=r"(r[1]), "=r"(r[2]), "=r"(r[3]) : "r"(addr));
}

// ---------------- T0: NCHW -> padded NHWC fp16 hi/lo ------------------------
__global__ __launch_bounds__(256) void t_half(const float* __restrict__ x){
    __shared__ float s[256][33];
    const int b = blockIdx.y;
    const int px0 = blockIdx.x*32;
    const int tid = threadIdx.x;
    const int pxl = tid & 31, cg = tid >> 5;
    const int p = px0 + pxl;
    const int ph = p / PP, pw = p % PP;
    const bool in = (p < NPX) && ph >= 1 && ph <= 128 && pw >= 1 && pw <= 128;
    const float* xp = x + (size_t)b*CN*HW + (size_t)(ph-1)*WN + (pw-1);
    #pragma unroll 8
    for (int i=0;i<32;i++){
        int c = i*8 + cg;
        s[c][pxl] = in ? xp[(size_t)c*HW] : 0.f;
    }
    __syncthreads();
    for (int j=0;j<32;j++){
        int px = px0 + j;
        if (px >= NPX) break;
        float v  = s[tid][j];
        __half hi = __float2half_rn(v);
        __half lo = __float2half_rn(v - __half2float(hi));
        size_t o = ((size_t)b*NPX + px)*CN + tid;
        g_xh[o] = hi;
        g_xl[o] = lo;
    }
}

// ---------------- K0: weight prep (fragment order) + w2t --------------------
// u32 element t: j=t&3, l=(t>>2)&31, ogp=(t>>7)&15, k16=(t>>11) (0..143,
// tap-major cin-minor).  og=ogp*2+(j>>1); oc=og*8+l/4;
// k = (k16%16)*16 + (j&1)*8 + (l%4)*2  (+0,+1); tap = k16/16
__global__ void k0_wprep(const float* __restrict__ w1,
                         const float* __restrict__ w2){
    int t = blockIdx.x*256 + threadIdx.x;
    if (t < 144*16*32*4){
        int j    = t & 3;
        int l    = (t>>2) & 31;
        int ogp  = (t>>7) & 15;
        int k16  = t >> 11;
        int tap  = k16 >> 4;
        int oc = (ogp*2 + (j>>1))*8 + (l>>2);
        int k  = (k16 & 15)*16 + (j&1)*8 + (l&3)*2;
        float v0 = w1[((size_t)oc*CN + k  )*9 + tap];
        float v1 = w1[((size_t)oc*CN + k+1)*9 + tap];
        __half h0 = __float2half_rn(v0);
        __half h1 = __float2half_rn(v1);
        __half l0 = __float2half_rn(v0 - __half2float(h0));
        __half l1 = __float2half_rn(v1 - __half2float(h1));
        ((uint32_t*)g_wfh)[t] = (uint32_t)__half_as_ushort(h0) |
                                ((uint32_t)__half_as_ushort(h1) << 16);
        ((uint32_t*)g_wfl)[t] = (uint32_t)__half_as_ushort(l0) |
                                ((uint32_t)__half_as_ushort(l1) << 16);
    }
    if (t < CN*NCH){
        int cin = t/NCH, oc = t%NCH;
        g_w2t[t] = w2[oc*CN + cin];
    }
}

// ---------------- K1: conv3x3 via mma.sync fp16 split ------------------------
// grid (128 h, 2 octile, 8 b); 256 threads = 8 warps (2M x 4N), warp m64n32.
// A: 3-stage cp.async ring, 64 cin/stage (128B rows), swizzle chunk^=(row&7);
// Ah/Al 16KB each = 32KB/stage, 96KB total -> 2 CTAs/SM. 36 g-iters.
// B: direct LDG.128 from fragment-ordered g_wfh/g_wfl (L1-resident).
#define STG_SZ 32768u
#define AL_OFF 16384u

__global__ __launch_bounds__(256,2) void kmma(const float* __restrict__ b1){
    extern __shared__ __align__(16) char smem[];
    const uint32_t sb = smem_u32(smem);
    const int tid  = threadIdx.x;
    const int lane = tid & 31, wid = tid >> 5;
    const int wm = wid >> 2, wn = wid & 3;
    const int h  = blockIdx.x;
    const int ocb = blockIdx.y * 128;
    const int bb = blockIdx.z;

    // A fill: row = tid>>1 (0..127, 128B rows), half=(tid&1) -> chunks 4h..4h+3
    const int lrow = tid >> 1, lhalf = tid & 1;
    const uint32_t fsw = (uint32_t)(lrow & 7);
    const int fc0 = 4*lhalf;

    auto load_stage = [&](int g, int buf){
        const int tap = g >> 2, kc = g & 3;            // kc: 64-channel chunk
        const int ky = tap/3, kx = tap%3;
        const uint32_t sbase = sb + buf*STG_SZ;
        const size_t apix = (size_t)bb*NPX + (size_t)(h + ky)*PP + kx + lrow;
        const size_t aoff = apix*CN + kc*64 + fc0*8;
        #pragma unroll
        for (int i=0;i<4;i++){
            const uint32_t dst = (uint32_t)lrow*128u + (((uint32_t)(fc0+i)) ^ fsw)*16u;
            cpa16(sbase          + dst, g_xh + aoff + i*8);
            cpa16(sbase + AL_OFF + dst, g_xl + aoff + i*8);
        }
        CP_COMMIT();
    };

    float acc[4][4][4];
    #pragma unroll
    for (int mt=0;mt<4;mt++)
        #pragma unroll
        for (int nt=0;nt<4;nt++)
            #pragma unroll
            for (int q=0;q<4;q++) acc[mt][nt][q] = 0.f;

    load_stage(0, 0);
    load_stage(1, 1);

    // A fragment addressing: row = wm*64+mt*16+(lane&15); swizzle key = lane&7
    const uint32_t rA  = (uint32_t)(lane & 15);
    const uint32_t sA  = (uint32_t)(lane & 7);
    const uint32_t cA0 = (uint32_t)(lane >> 4);
    const int ogp_base = blockIdx.y*8 + wn*2;

    for (int g=0; g<36; g++){
        const int buf = g % 3;
        CP_WAIT1();
        __syncthreads();
        if (g + 2 < 36) load_stage(g+2, (g+2)%3);

        const uint32_t sbase  = sb + buf*STG_SZ;
        const uint32_t aBaseH = sbase          + (uint32_t)(wm*64 + (int)rA)*128u;
        const uint32_t aBaseL = sbase + AL_OFF + (uint32_t)(wm*64 + (int)rA)*128u;

        #pragma unroll
        for (int q=0; q<4; q++){
            // B fragments: direct LDG.128, fragment-ordered (k16 = g*4+q)
            const int fb = ((g*4 + q)*16 + ogp_base)*32 + lane;
            const uint4 bq0 = __ldg(&g_wfh[fb]);
            const uint4 bq1 = __ldg(&g_wfh[fb + 32]);
            const uint4 cq0 = __ldg(&g_wfl[fb]);
            const uint4 cq1 = __ldg(&g_wfl[fb + 32]);
            uint32_t bh[4][2] = {{bq0.x,bq0.y},{bq0.z,bq0.w},{bq1.x,bq1.y},{bq1.z,bq1.w}};
            uint32_t bl[4][2] = {{cq0.x,cq0.y},{cq0.z,cq0.w},{cq1.x,cq1.y},{cq1.z,cq1.w}};

            const uint32_t gA = ((uint32_t)(q*2) + cA0) ^ sA;
            uint32_t ah[4][4], al[4][4];
            #pragma unroll
            for (int mt=0;mt<4;mt++){
                ldm4(ah[mt], aBaseH + (uint32_t)(mt*16)*128u + gA*16u);
                ldm4(al[mt], aBaseL + (uint32_t)(mt*16)*128u + gA*16u);
            }
            #pragma unroll
            for (int mt=0;mt<4;mt++)
                #pragma unroll
                for (int nt=0;nt<4;nt++){
                    mma16816(acc[mt][nt], ah[mt], bh[nt]);
                    mma16816(acc[mt][nt], ah[mt], bl[nt]);
                    mma16816(acc[mt][nt], al[mt], bh[nt]);
                }
        }
    }
    CP_WAIT0();

    // epilogue: bias + relu -> y NHWC
    #pragma unroll
    for (int nt=0;nt<4;nt++){
        const int cc = ocb + wn*32 + nt*8 + (lane & 3)*2;
        const float bz0 = b1[cc], bz1 = b1[cc+1];
        #pragma unroll
        for (int mt=0;mt<4;mt++){
            const int w = wm*64 + mt*16 + (lane >> 2);
            const size_t pix = (size_t)bb*HW + (size_t)h*WN + w;
            float2 v0, v1;
            v0.x = fmaxf(acc[mt][nt][0] + bz0, 0.f);
            v0.y = fmaxf(acc[mt][nt][1] + bz1, 0.f);
            v1.x = fmaxf(acc[mt][nt][2] + bz0, 0.f);
            v1.y = fmaxf(acc[mt][nt][3] + bz1, 0.f);
            *(float2*)&g_y[pix*CN + cc]     = v0;
            *(float2*)&g_y[(pix+8)*CN + cc] = v1;
        }
    }
}

// ---------------- K2: conv1x1 + bias + softmax stats + logits out ----------
__global__ __launch_bounds__(256,2) void k2_conv1(const float* __restrict__ b2,
                                                  float* __restrict__ out){
    __shared__ __align__(16) float ws2[32][84];
    const int tid = threadIdx.x;
    const int gp  = blockIdx.x*256 + tid;
    const int b   = gp >> 14, hw = gp & (HW-1);

    float acc[NCH];
    #pragma unroll
    for (int o=0;o<NCH;o++) acc[o] = 0.f;

    const float* yb = g_y + (size_t)gp*CN;      // NHWC: contiguous 256 per pixel
    for (int cc=0; cc<CN; cc+=32){
        __syncthreads();
        #pragma unroll
        for (int i=tid; i<32*NCH; i+=256)
            ws2[i/NCH][i%NCH] = g_w2t[(cc + i/NCH)*NCH + (i%NCH)];
        __syncthreads();
        #pragma unroll
        for (int j=0;j<8;j++){
            const float4 v4 = *(const float4*)(yb + cc + j*4);
            const float vv[4] = {v4.x, v4.y, v4.z, v4.w};
            #pragma unroll
            for (int u=0;u<4;u++){
                const int cl = j*4 + u;
                const float v = vv[u];
                #pragma unroll
                for (int o4=0;o4<20;o4++){
                    float4 w4 = *(const float4*)&ws2[cl][o4*4];
                    acc[o4*4+0] += v*w4.x; acc[o4*4+1] += v*w4.y;
                    acc[o4*4+2] += v*w4.z; acc[o4*4+3] += v*w4.w;
                }
                acc[80] += v*ws2[cl][80];
            }
        }
    }
    #pragma unroll
    for (int o=0;o<NCH;o++) acc[o] += b2[o];

    float m = acc[0];
    #pragma unroll
    for (int o=1;o<NCH;o++) m = fmaxf(m, acc[o]);
    float s = 0.f;
    #pragma unroll
    for (int o=0;o<NCH;o++) s += __expf(acc[o]-m);
    int cls = 0; float best = acc[0];
    #pragma unroll
    for (int o=1;o<NCLS;o++) if (acc[o] > best){ best = acc[o]; cls = o; }

    g_pstar[gp] = __expf(best - m)/s;
    g_cls[gp]   = cls;

    float* lo = out + 409600 + (size_t)b*NCH*HW + hw;
    #pragma unroll
    for (int o=0;o<NCH;o++) lo[(size_t)o*HW] = acc[o];
}

// ---------------- K3: local-max boost + score map --------------------------
__global__ void k3_boost(){
    const int gp = blockIdx.x*256 + threadIdx.x;
    const int b = gp>>14, hw = gp&(HW-1);
    const int h = hw>>7,  w  = hw&127;
    const float p = g_pstar[gp];
    const int   c = g_cls[gp];
    bool ok = (p >= 1e-6f);
    #pragma unroll
    for (int dy=-1; dy<=1; dy++)
        #pragma unroll
        for (int dx=-1; dx<=1; dx++){
            if (dy==0 && dx==0) continue;
            int nh = h+dy, nw = w+dx;
            if (nh<0 || nh>=HN || nw<0 || nw>=WN) continue;
            int n = (b<<14) + nh*WN + nw;
            if (g_cls[n]==c && p < g_pstar[n]) ok = false;
        }
    g_scores[gp] = p + (ok ? 1.f : 0.f);
}

// ---------------- K4: per-batch top-100 via bitonic sort -------------------
__global__ void k4_topk(){
    extern __shared__ unsigned long long sk[];
    const int N = HW;
    const int b = blockIdx.x, tid = threadIdx.x;
    for (int i=tid; i<N; i+=1024){
        unsigned sb2 = __float_as_uint(g_scores[(b<<14)+i]);
        sk[i] = ((unsigned long long)sb2<<32) | (unsigned)(0xFFFFFFFFu - (unsigned)i);
    }
    __syncthreads();
    for (int k=2; k<=N; k<<=1){
        for (int j=k>>1; j>0; j>>=1){
            for (int i=tid; i<N; i+=1024){
                int ixj = i^j;
                if (ixj > i){
                    unsigned long long a = sk[i], c = sk[ixj];
                    bool up = (i&k)==0;
                    if (up ? (a<c) : (a>c)){ sk[i]=c; sk[ixj]=a; }
                }
            }
            __syncthreads();
        }
    }
    if (tid < TK){
        unsigned low = (unsigned)sk[tid];
        g_topidx[b*TK + tid] = (int)(0xFFFFFFFFu - low);
    }
}

// ---------------- K5: gather proposals + pos embeddings --------------------
__global__ void k5_gather(const float* __restrict__ x,
                          const float* __restrict__ pe,
                          float* __restrict__ out){
    const int t = blockIdx.x*256 + threadIdx.x;
    if (t >= BN*CN*TK) return;
    const int k = t % TK;
    const int c = (t / TK) % CN;
    const int b = t / (TK*CN);
    const int idx = g_topidx[b*TK + k];
    out[t]            = x [(size_t)(b*CN + c)*HW + idx];
    out[BN*CN*TK + t] = pe[(size_t)c*HW + idx];
}

// ---------------- launch ----------------------------------------------------
extern "C" void kernel_launch(void* const* d_in, const int* in_sizes, int n_in,
                              void* d_out, int out_size){
    const float* x  = (const float*)d_in[0];
    const float* pe = (const float*)d_in[1];
    const float* w1 = (const float*)d_in[2];
    const float* b1 = (const float*)d_in[3];
    const float* w2 = (const float*)d_in[4];
    const float* b2 = (const float*)d_in[5];
    float* out = (float*)d_out;

    cudaFuncSetAttribute(kmma,   cudaFuncAttributeMaxDynamicSharedMemorySize, 3*STG_SZ);
    cudaFuncSetAttribute(k4_topk, cudaFuncAttributeMaxDynamicSharedMemorySize, 131072);

    dim3 gt((NPX + 31)/32, BN);
    t_half<<<gt, 256>>>(x);
    k0_wprep<<<(144*16*32*4 + 255)/256, 256>>>(w1, w2);

    dim3 gg(128, 2, BN);
    kmma<<<gg, 256, 3*STG_SZ>>>(b1);

    k2_conv1<<<(BN*HW)/256, 256>>>(b2, out);
    k3_boost<<<(BN*HW)/256, 256>>>();
    k4_topk<<<BN, 1024, 131072>>>();
    k5_gather<<<(BN*CN*TK + 255)/256, 256>>>(x, pe, out);
}